// round 11
// baseline (speedup 1.0000x reference)
#include <cuda_runtime.h>
#include <cuda_fp16.h>
#include <cstdint>

#define MAXB 8192
#define DD   128
#define NTH  512
#define NSM  148
#define ROWT 256
#define COLT 64

// ---------------- global scratch (no allocations allowed) ----------------
// pre-swizzled tile images (written by prep, bulk-copied by main)
__device__ __align__(1024) unsigned char g_qtile[2 * 1024 * 1024]; // 32 blks x 64KB (Q fp16)
__device__ __align__(1024) unsigned char g_atile[4 * 1024 * 1024]; // 128 blks x 32KB (A hi+lo)
__device__ float g_den[MAXB], g_num[MAXB];
__device__ int   g_emax[MAXB], g_emp[MAXB];
__device__ int   g_done;

// ---------------- smem layout ----------------
#define SM_Q     0                        // 64KB: h0 32K | h1 32K
#define SM_A(b)  (65536 + (b) * 32768)    // 4 bufs: hi h0 8K|hi h1 8K|lo h0|lo h1
#define SM_IDS(s) (196608 + (s) * 256)    // 4 slots x 64 ids
#define SM_RNK(s) (197632 + (s) * 256)
#define SM_BAR   198656                   // barQ +0, full[4] +8.., empty[4] +40.., flag +72
#define SM_RED   198784                   // 8KB reduction area
#define SMEM_TOTAL 206976

static __device__ __forceinline__ unsigned su32(const void* p) {
    return (unsigned)__cvta_generic_to_shared(p);
}
static __device__ __forceinline__ void mbar_init(uint32_t bar, int cnt) {
    asm volatile("mbarrier.init.shared.b64 [%0], %1;" :: "r"(bar), "r"(cnt) : "memory");
}
static __device__ __forceinline__ void mbar_expect(uint32_t bar, uint32_t bytes) {
    asm volatile("mbarrier.arrive.expect_tx.shared.b64 _, [%0], %1;"
                 :: "r"(bar), "r"(bytes) : "memory");
}
static __device__ __forceinline__ void mbar_arrive(uint32_t bar) {
    asm volatile("mbarrier.arrive.release.cta.shared.b64 _, [%0];"
                 :: "r"(bar) : "memory");
}
static __device__ __forceinline__ void bulk_g2s(uint32_t dst, const void* src,
                                                uint32_t bytes, uint32_t bar) {
    asm volatile(
        "cp.async.bulk.shared::cta.global.mbarrier::complete_tx::bytes [%0], [%1], %2, [%3];"
        :: "r"(dst), "l"(src), "r"(bytes), "r"(bar) : "memory");
}
static __device__ __forceinline__ void mbar_wait(uint32_t bar, int parity) {
    asm volatile(
        "{\n\t.reg .pred P;\n\t"
        "WL_%=:\n\t"
        "mbarrier.try_wait.parity.shared.b64 P, [%0], %1;\n\t"
        "@P bra.uni WD_%=;\n\t"
        "bra.uni WL_%=;\n\t"
        "WD_%=:\n\t}"
        :: "r"(bar), "r"(parity) : "memory");
}
static __device__ __forceinline__ float ex2f(float x) {
    float r;
    asm("ex2.approx.ftz.f32 %0, %1;" : "=f"(r) : "f"(x));
    return r;
}

// swizzled offset inside one k-half region (row r, 16B chunk c 0..7)
static __device__ __forceinline__ int halfoff(int r, int c) {
    return r * 128 + ((c ^ (r & 7)) << 4);
}

#define LDSM4(rg, ad) asm volatile( \
    "ldmatrix.sync.aligned.m8n8.x4.shared.b16 {%0,%1,%2,%3}, [%4];" \
    : "=r"((rg)[0]), "=r"((rg)[1]), "=r"((rg)[2]), "=r"((rg)[3]) : "r"(ad))
#define MMAI(dd, aa, bb) asm volatile( \
    "mma.sync.aligned.m16n8k16.row.col.f32.f16.f16.f32 " \
    "{%0,%1,%2,%3}, {%4,%5,%6,%7}, {%8,%9}, {%0,%1,%2,%3};" \
    : "+f"((dd)[0]), "+f"((dd)[1]), "+f"((dd)[2]), "+f"((dd)[3]) \
    : "r"((aa)[0]), "r"((aa)[1]), "r"((aa)[2]), "r"((aa)[3]), \
      "r"((bb)[0]), "r"((bb)[1]))

// ---------- prep: fp32 -> fp16 (Q prescaled; A hi/lo) pre-swizzled ----------
extern "C" __global__ void mpl_prep(const float4* __restrict__ Q4,
                                    const float4* __restrict__ A4, int n8) {
    int i = blockIdx.x * blockDim.x + threadIdx.x;   // one 16B fp16 chunk (8 elems)
    if (i < n8) {
        float4 qa = Q4[2 * i], qb = Q4[2 * i + 1];
        float4 aa = A4[2 * i], ab = A4[2 * i + 1];
        float qv[8] = {qa.x, qa.y, qa.z, qa.w, qb.x, qb.y, qb.z, qb.w};
        float av[8] = {aa.x, aa.y, aa.z, aa.w, ab.x, ab.y, ab.z, ab.w};
        __align__(16) __half qh8[8], ah8[8], al8[8];
        #pragma unroll
        for (int k = 0; k < 8; k++) {
            qh8[k] = __float2half(qv[k] * 1.4426950408889634f);  // fold log2e
            __half h2 = __float2half(av[k]);
            ah8[k] = h2;
            al8[k] = __float2half(av[k] - __half2float(h2));
        }
        const int r = i >> 4, cc = i & 15;
        {   // Q tile image: blk 64KB = [h0 32K | h1 32K]
            int rt = r >> 8, rl = r & 255;
            size_t off = (size_t)rt * 65536 + ((cc >> 3) << 15) + halfoff(rl, cc & 7);
            *(uint4*)(g_qtile + off) = *(uint4*)qh8;
        }
        {   // A tile image: blk 32KB = [hi h0|hi h1|lo h0|lo h1] x 8KB
            int j = r >> 6, rl = r & 63;
            size_t off = (size_t)j * 32768 + ((cc >> 3) << 13) + halfoff(rl, cc & 7);
            *(uint4*)(g_atile + off)         = *(uint4*)ah8;
            *(uint4*)(g_atile + off + 16384) = *(uint4*)al8;
        }
    }
    if (i < MAXB) {
        g_den[i] = 0.f; g_num[i] = 0.f; g_emax[i] = 0; g_emp[i] = 0;
    }
    if (i == 0) g_done = 0;
}

static __device__ __forceinline__ void issue_a(uint32_t smb, int slot, int col,
                                               const int* qid, const float* rnk) {
    const uint32_t bar = smb + SM_BAR + 8 + slot * 8;
    mbar_expect(bar, 32768 + 512);
    const unsigned char* src = g_atile + (size_t)col * 32768;
    bulk_g2s(smb + SM_A(slot),         src,         16384, bar);
    bulk_g2s(smb + SM_A(slot) + 16384, src + 16384, 16384, bar);
    bulk_g2s(smb + SM_IDS(slot), qid + col * COLT, 256, bar);
    bulk_g2s(smb + SM_RNK(slot), rnk + col * COLT, 256, bar);
}

// -------------------- main: 16-warp persistent fused GEMM + softmax-ratio --------------------
extern "C" __global__ void __launch_bounds__(NTH, 1)
mpl_main(const int* __restrict__ qid, const float* __restrict__ rnk,
         float* __restrict__ out, int B, int osz) {
    extern __shared__ __align__(128) char sm[];
    const uint32_t smb = su32(sm);
    const int tid = threadIdx.x, l = tid & 31, wid = tid >> 5;
    const int wm = wid >> 1, wn = wid & 1;       // 8x2 warp grid (32x32 per warp)
    const int ncol = B / COLT, nrow = B / ROWT;
    const long long total = (long long)nrow * ncol;
    const int start = (int)(total * blockIdx.x / NSM);
    const int end   = (int)(total * (blockIdx.x + 1) / NSM);
    const int njobs = end - start;

    const uint32_t barQ = smb + SM_BAR;
    if (tid == 0) {
        mbar_init(barQ, 1);
        #pragma unroll
        for (int b = 0; b < 4; b++) {
            mbar_init(smb + SM_BAR + 8 + b * 8, 1);    // full (tx)
            mbar_init(smb + SM_BAR + 40 + b * 8, 16);  // empty (16 warps)
        }
    }
    __syncthreads();

    // prologue: prefetch first 2 A tiles (buffers virgin, no empty-wait)
    if (tid == 0) {
        #pragma unroll
        for (int k = 0; k < 2; k++)
            if (k < njobs) issue_a(smb, k, (start + k) % ncol, qid, rnk);
    }

    const int x = l & 7, subA = l >> 4, subB = (l >> 3) & 1;
    int rAoff[2], rBoff[2];
    #pragma unroll
    for (int mi = 0; mi < 2; mi++) rAoff[mi] = (wm * 32 + mi * 16 + (l & 15)) * 128;
    #pragma unroll
    for (int n2 = 0; n2 < 2; n2++)
        rBoff[n2] = (wn * 32 + n2 * 16 + ((l >> 4) << 3) + (l & 7)) * 128;

    // producer empty-wait parities: slots 0,1 first waited after 1st use (p=0);
    // slots 2,3 first waited before any use (p=1, immediate)
    int eph0 = 0, eph1 = 0, eph2 = 1, eph3 = 1;

    int qph = 0;
    int tt = 0;          // flat tile counter: slot = tt&3, full phase = (tt>>2)&1
    int pos = start;
    while (pos < end) {
        const int rt = pos / ncol;
        const int c0 = pos - rt * ncol;
        const int c1 = min(ncol, c0 + (end - pos));
        pos += c1 - c0;
        const int rowbase = rt * ROWT;

        if (tid == 0) {       // Q tile for this segment (prior segment fully synced)
            mbar_expect(barQ, 65536);
            const unsigned char* qs = g_qtile + (size_t)rt * 65536;
            #pragma unroll
            for (int k = 0; k < 4; k++)
                bulk_g2s(smb + SM_Q + k * 16384, qs + k * 16384, 16384, barQ);
        }

        int qrow[4];
        #pragma unroll
        for (int mi = 0; mi < 2; mi++)
            #pragma unroll
            for (int h = 0; h < 2; h++)
                qrow[mi * 2 + h] = qid[rowbase + wm * 32 + mi * 16 + (l >> 2) + h * 8];

        float den[4], num[4], emax[4], emp[4];
        #pragma unroll
        for (int ri = 0; ri < 4; ri++) {
            den[ri] = 0.f; num[ri] = 0.f; emax[ri] = 0.f; emp[ri] = 0.f;
        }

        mbar_wait(barQ, qph); qph ^= 1;

        for (int j = c0; j < c1; j++, tt++) {
            const int slot = tt & 3;
            mbar_wait(smb + SM_BAR + 8 + slot * 8, (tt >> 2) & 1);  // full

            // producer: issue tile tt+2 after freeing check (thread0 only)
            if (tid == 0 && tt + 2 < njobs) {
                const int s2 = (tt + 2) & 3;
                int ep = (s2 == 0) ? eph0 : (s2 == 1) ? eph1 : (s2 == 2) ? eph2 : eph3;
                mbar_wait(smb + SM_BAR + 40 + s2 * 8, ep);
                if (s2 == 0) eph0 ^= 1; else if (s2 == 1) eph1 ^= 1;
                else if (s2 == 2) eph2 ^= 1; else eph3 ^= 1;
                issue_a(smb, s2, (start + tt + 2) % ncol, qid, rnk);
            }

            const uint32_t sma = smb + SM_A(slot);
            const uint32_t smq = smb + SM_Q;

            float acc[2][4][4];
            #pragma unroll
            for (int mi = 0; mi < 2; mi++)
                #pragma unroll
                for (int ni = 0; ni < 4; ni++)
                    #pragma unroll
                    for (int k = 0; k < 4; k++) acc[mi][ni][k] = 0.f;

            #pragma unroll
            for (int s = 0; s < 8; s++) {
                const int haQ = (s >> 2) << 15;          // Q k-half stride 32KB
                const int haA = (s >> 2) << 13;          // A k-half stride 8KB
                const int cb = (s & 3) << 1;
                const int tA = (((cb | subA) ^ x) << 4) + haQ;
                const int tB = (((cb | subB) ^ x) << 4) + haA;
                uint32_t ah[2][4], bh[2][4], bl[2][4];
                #pragma unroll
                for (int mi = 0; mi < 2; mi++)
                    LDSM4(ah[mi], smq + rAoff[mi] + tA);
                #pragma unroll
                for (int n2 = 0; n2 < 2; n2++) {
                    uint32_t bd = sma + rBoff[n2] + tB;
                    LDSM4(bh[n2], bd);
                    LDSM4(bl[n2], bd + 16384);           // A lo region
                }
                #pragma unroll
                for (int mi = 0; mi < 2; mi++)
                    #pragma unroll
                    for (int ni = 0; ni < 4; ni++) {
                        const uint32_t* bhf = &bh[ni >> 1][(ni & 1) * 2];
                        const uint32_t* blf = &bl[ni >> 1][(ni & 1) * 2];
                        MMAI(acc[mi][ni], ah[mi], bhf);   // q * a_hi
                        MMAI(acc[mi][ni], ah[mi], blf);   // q * a_lo
                    }
            }

            // ---- epilogue (overlaps other warps' MMA — no CTA barrier) ----
            {
                const int*   idsb = (const int*)(sm + SM_IDS(slot));
                const float* rkb  = (const float*)(sm + SM_RNK(slot));
                int ids8[8];
                float w8[8];
                #pragma unroll
                for (int ni = 0; ni < 4; ni++)
                    #pragma unroll
                    for (int jj = 0; jj < 2; jj++) {
                        int cl = wn * 32 + ni * 8 + (l & 3) * 2 + jj;
                        ids8[ni * 2 + jj] = idsb[cl];
                        w8[ni * 2 + jj]   = 1.0f - 0.1f * rkb[cl];
                    }
                #pragma unroll
                for (int mi = 0; mi < 2; mi++)
                    #pragma unroll
                    for (int h = 0; h < 2; h++) {
                        const int ri = mi * 2 + h;
                        #pragma unroll
                        for (int ni = 0; ni < 4; ni++)
                            #pragma unroll
                            for (int jj = 0; jj < 2; jj++) {
                                const int cj = ni * 2 + jj;
                                float e = ex2f(acc[mi][ni][h * 2 + jj]);
                                den[ri] += e;
                                float em = (ids8[cj] == qrow[ri]) ? e : 0.0f;
                                num[ri] = fmaf(w8[cj], em, num[ri]);
                                emax[ri] = fmaxf(emax[ri], e);
                                emp[ri]  = fmaxf(emp[ri], em);
                            }
                    }
            }
            if (l == 0) mbar_arrive(smb + SM_BAR + 40 + slot * 8);  // warp done w/ slot
        }

        // ---- reduce: lane quads, then 2 wn warps via smem, then atomics ----
        #pragma unroll
        for (int ri = 0; ri < 4; ri++) {
            #pragma unroll
            for (int o = 1; o <= 2; o <<= 1) {
                den[ri]  += __shfl_xor_sync(0xffffffffu, den[ri], o);
                num[ri]  += __shfl_xor_sync(0xffffffffu, num[ri], o);
                emax[ri]  = fmaxf(emax[ri], __shfl_xor_sync(0xffffffffu, emax[ri], o));
                emp[ri]   = fmaxf(emp[ri],  __shfl_xor_sync(0xffffffffu, emp[ri],  o));
            }
        }
        float* sden = (float*)(sm + SM_RED);              // [2][256]
        float* snum = (float*)(sm + SM_RED + 2048);
        float* smx  = (float*)(sm + SM_RED + 4096);
        float* smp  = (float*)(sm + SM_RED + 6144);
        __syncthreads();    // all warps done with tile loop before staging
        if ((l & 3) == 0) {
            #pragma unroll
            for (int mi = 0; mi < 2; mi++)
                #pragma unroll
                for (int h = 0; h < 2; h++) {
                    int ri = mi * 2 + h;
                    int row = wm * 32 + mi * 16 + (l >> 2) + h * 8;
                    sden[wn * 256 + row] = den[ri];
                    snum[wn * 256 + row] = num[ri];
                    smx [wn * 256 + row] = emax[ri];
                    smp [wn * 256 + row] = emp[ri];
                }
        }
        __syncthreads();
        if (tid < 256) {
            float d = 0.f, n = 0.f, mx = 0.f, mp = 0.f;
            #pragma unroll
            for (int w = 0; w < 2; w++) {
                d += sden[w * 256 + tid];
                n += snum[w * 256 + tid];
                mx = fmaxf(mx, smx[w * 256 + tid]);
                mp = fmaxf(mp, smp[w * 256 + tid]);
            }
            atomicAdd(&g_den[rowbase + tid], d);
            atomicAdd(&g_num[rowbase + tid], n);
            atomicMax(&g_emax[rowbase + tid], __float_as_int(mx));
            atomicMax(&g_emp[rowbase + tid], __float_as_int(mp));
        }
        __syncthreads();   // Q buf free before next segment's TMA
    }

    // ---- last CTA computes loss + accuracy ----
    __threadfence();
    int* sflag = (int*)(sm + SM_BAR + 72);
    if (tid == 0) *sflag = (atomicAdd(&g_done, 1) == NSM - 1) ? 1 : 0;
    __syncthreads();
    if (*sflag) {
        float ls = 0.f;
        int cs = 0;
        for (int r = tid; r < B; r += NTH) {
            float d  = __ldcg(&g_den[r]);
            float n  = __ldcg(&g_num[r]);
            float mx = __int_as_float(__ldcg(&g_emax[r]));
            float mp = __int_as_float(__ldcg(&g_emp[r]));
            ls += -logf(n / d + 1e-8f);
            cs += (mp >= mx) ? 1 : 0;
        }
        float* sf = (float*)(sm + SM_RED);
        int*   si = (int*)(sm + SM_RED + 2048);
        sf[tid] = ls; si[tid] = cs;
        __syncthreads();
        for (int o = NTH / 2; o > 0; o >>= 1) {
            if (tid < o) { sf[tid] += sf[tid + o]; si[tid] += si[tid + o]; }
            __syncthreads();
        }
        if (tid == 0) {
            out[0] = sf[0] / (float)B;
            if (osz > 1) out[1] = (float)si[0] / (float)B;
        }
    }
}

extern "C" void kernel_launch(void* const* d_in, const int* in_sizes, int n_in,
                              void* d_out, int out_size) {
    const float* Q   = (const float*)d_in[0];
    const float* A   = (const float*)d_in[1];
    const int*   qid = (const int*)d_in[2];
    const float* rnk = (const float*)d_in[3];
    const int B = in_sizes[2];
    const int n8 = B * DD / 8;

    mpl_prep<<<(n8 + 255) / 256, 256>>>((const float4*)Q, (const float4*)A, n8);

    cudaFuncSetAttribute(mpl_main, cudaFuncAttributeMaxDynamicSharedMemorySize,
                         SMEM_TOTAL);
    mpl_main<<<NSM, NTH, SMEM_TOTAL>>>(qid, rnk, (float*)d_out, B, out_size);
}

// round 12
// speedup vs baseline: 1.4211x; 1.4211x over previous
#include <cuda_runtime.h>
#include <cuda_fp16.h>
#include <cstdint>

#define MAXB 8192
#define DD   128
#define NTH  512
#define NSM  148
#define ROWT 256
#define COLT 64

// ---------------- global scratch (no allocations allowed) ----------------
// pre-swizzled tile images (written by prep, bulk-copied by main)
__device__ __align__(1024) unsigned char g_qtile[2 * 1024 * 1024]; // 32 blks x 64KB (Q fp16)
__device__ __align__(1024) unsigned char g_atile[2 * 1024 * 1024]; // 128 blks x 16KB (A fp16)
__device__ float g_den[MAXB], g_num[MAXB];
__device__ int   g_emax[MAXB], g_emp[MAXB];
__device__ int   g_done;

// ---------------- smem layout ----------------
#define SM_Q     0                        // 64KB: h0 32K | h1 32K
#define SM_A(b)  (65536 + (b) * 16384)    // 4 bufs: h0 8K | h1 8K
#define SM_IDS(s) (131072 + (s) * 256)    // 4 slots x 64 ids
#define SM_RNK(s) (132096 + (s) * 256)
#define SM_BAR   133120                   // barQ +0, A full bars +8..+39, flag +48
#define SM_RED   133184                   // 8KB reduction area
#define SMEM_TOTAL 141440

static __device__ __forceinline__ unsigned su32(const void* p) {
    return (unsigned)__cvta_generic_to_shared(p);
}
static __device__ __forceinline__ void mbar_init(uint32_t bar, int cnt) {
    asm volatile("mbarrier.init.shared.b64 [%0], %1;" :: "r"(bar), "r"(cnt) : "memory");
}
static __device__ __forceinline__ void mbar_expect(uint32_t bar, uint32_t bytes) {
    asm volatile("mbarrier.arrive.expect_tx.shared.b64 _, [%0], %1;"
                 :: "r"(bar), "r"(bytes) : "memory");
}
static __device__ __forceinline__ void bulk_g2s(uint32_t dst, const void* src,
                                                uint32_t bytes, uint32_t bar) {
    asm volatile(
        "cp.async.bulk.shared::cta.global.mbarrier::complete_tx::bytes [%0], [%1], %2, [%3];"
        :: "r"(dst), "l"(src), "r"(bytes), "r"(bar) : "memory");
}
static __device__ __forceinline__ void mbar_wait(uint32_t bar, int parity) {
    asm volatile(
        "{\n\t.reg .pred P;\n\t"
        "WL_%=:\n\t"
        "mbarrier.try_wait.parity.shared.b64 P, [%0], %1;\n\t"
        "@P bra.uni WD_%=;\n\t"
        "bra.uni WL_%=;\n\t"
        "WD_%=:\n\t}"
        :: "r"(bar), "r"(parity) : "memory");
}
static __device__ __forceinline__ float ex2f(float x) {
    float r;
    asm("ex2.approx.ftz.f32 %0, %1;" : "=f"(r) : "f"(x));
    return r;
}

// swizzled offset inside one k-half region (row r, 16B chunk c 0..7)
static __device__ __forceinline__ int halfoff(int r, int c) {
    return r * 128 + ((c ^ (r & 7)) << 4);
}

#define LDSM4(rg, ad) asm volatile( \
    "ldmatrix.sync.aligned.m8n8.x4.shared.b16 {%0,%1,%2,%3}, [%4];" \
    : "=r"((rg)[0]), "=r"((rg)[1]), "=r"((rg)[2]), "=r"((rg)[3]) : "r"(ad))
#define MMAI(dd, aa, bb) asm volatile( \
    "mma.sync.aligned.m16n8k16.row.col.f32.f16.f16.f32 " \
    "{%0,%1,%2,%3}, {%4,%5,%6,%7}, {%8,%9}, {%0,%1,%2,%3};" \
    : "+f"((dd)[0]), "+f"((dd)[1]), "+f"((dd)[2]), "+f"((dd)[3]) \
    : "r"((aa)[0]), "r"((aa)[1]), "r"((aa)[2]), "r"((aa)[3]), \
      "r"((bb)[0]), "r"((bb)[1]))

// ---------- prep: fp32 -> fp16 (Q prescaled by log2(e); A plain) pre-swizzled ----------
extern "C" __global__ void mpl_prep(const float4* __restrict__ Q4,
                                    const float4* __restrict__ A4, int n8) {
    int i = blockIdx.x * blockDim.x + threadIdx.x;   // one 16B fp16 chunk (8 elems)
    if (i < n8) {
        float4 qa = Q4[2 * i], qb = Q4[2 * i + 1];
        float4 aa = A4[2 * i], ab = A4[2 * i + 1];
        float qv[8] = {qa.x, qa.y, qa.z, qa.w, qb.x, qb.y, qb.z, qb.w};
        float av[8] = {aa.x, aa.y, aa.z, aa.w, ab.x, ab.y, ab.z, ab.w};
        __align__(16) __half qh8[8], ah8[8];
        #pragma unroll
        for (int k = 0; k < 8; k++) {
            qh8[k] = __float2half(qv[k] * 1.4426950408889634f);  // fold log2e
            ah8[k] = __float2half(av[k]);
        }
        const int r = i >> 4, cc = i & 15;
        {   // Q tile image: blk 64KB = [h0 32K | h1 32K]
            int rt = r >> 8, rl = r & 255;
            size_t off = (size_t)rt * 65536 + ((cc >> 3) << 15) + halfoff(rl, cc & 7);
            *(uint4*)(g_qtile + off) = *(uint4*)qh8;
        }
        {   // A tile image: blk 16KB = [h0 8K | h1 8K]
            int j = r >> 6, rl = r & 63;
            size_t off = (size_t)j * 16384 + ((cc >> 3) << 13) + halfoff(rl, cc & 7);
            *(uint4*)(g_atile + off) = *(uint4*)ah8;
        }
    }
    if (i < MAXB) {
        g_den[i] = 0.f; g_num[i] = 0.f; g_emax[i] = 0; g_emp[i] = 0;
    }
    if (i == 0) g_done = 0;
}

static __device__ __forceinline__ void issue_a(uint32_t smb, int slot, int col,
                                               const int* qid, const float* rnk) {
    const uint32_t bar = smb + SM_BAR + 8 + slot * 8;
    mbar_expect(bar, 16384 + 512);
    bulk_g2s(smb + SM_A(slot), g_atile + (size_t)col * 16384, 16384, bar);
    bulk_g2s(smb + SM_IDS(slot), qid + col * COLT, 256, bar);
    bulk_g2s(smb + SM_RNK(slot), rnk + col * COLT, 256, bar);
}

// -------------------- main: 16-warp persistent fused GEMM + softmax-ratio --------------------
extern "C" __global__ void __launch_bounds__(NTH, 1)
mpl_main(const int* __restrict__ qid, const float* __restrict__ rnk,
         float* __restrict__ out, int B, int osz) {
    extern __shared__ __align__(128) char sm[];
    const uint32_t smb = su32(sm);
    const int tid = threadIdx.x, l = tid & 31, wid = tid >> 5;
    const int wm = wid >> 1, wn = wid & 1;       // 8x2 warp grid (32x32 per warp)
    const int ncol = B / COLT, nrow = B / ROWT;
    const long long total = (long long)nrow * ncol;
    const int start = (int)(total * blockIdx.x / NSM);
    const int end   = (int)(total * (blockIdx.x + 1) / NSM);
    const int njobs = end - start;

    const uint32_t barQ = smb + SM_BAR;
    if (tid == 0) {
        mbar_init(barQ, 1);
        #pragma unroll
        for (int b = 0; b < 4; b++) mbar_init(smb + SM_BAR + 8 + b * 8, 1);
    }
    __syncthreads();

    // prologue: prefetch first 3 A tiles
    if (tid == 0) {
        #pragma unroll
        for (int k = 0; k < 3; k++)
            if (k < njobs) issue_a(smb, k & 3, (start + k) % ncol, qid, rnk);
    }

    const int x = l & 7, subA = l >> 4, subB = (l >> 3) & 1;
    int rAoff[2], rBoff[2];
    #pragma unroll
    for (int mi = 0; mi < 2; mi++) rAoff[mi] = (wm * 32 + mi * 16 + (l & 15)) * 128;
    #pragma unroll
    for (int n2 = 0; n2 < 2; n2++)
        rBoff[n2] = (wn * 32 + n2 * 16 + ((l >> 4) << 3) + (l & 7)) * 128;

    int qph = 0;
    int tt = 0;          // flat tile counter: slot = tt&3, phase = (tt>>2)&1
    int pos = start;
    while (pos < end) {
        const int rt = pos / ncol;
        const int c0 = pos - rt * ncol;
        const int c1 = min(ncol, c0 + (end - pos));
        pos += c1 - c0;
        const int rowbase = rt * ROWT;

        if (tid == 0) {       // Q tile for this segment (prior segment fully synced)
            mbar_expect(barQ, 65536);
            const unsigned char* qs = g_qtile + (size_t)rt * 65536;
            #pragma unroll
            for (int k = 0; k < 4; k++)
                bulk_g2s(smb + SM_Q + k * 16384, qs + k * 16384, 16384, barQ);
        }

        int qrow[4];
        #pragma unroll
        for (int mi = 0; mi < 2; mi++)
            #pragma unroll
            for (int h = 0; h < 2; h++)
                qrow[mi * 2 + h] = qid[rowbase + wm * 32 + mi * 16 + (l >> 2) + h * 8];

        float den[4], num[4], emax[4], emp[4];
        #pragma unroll
        for (int ri = 0; ri < 4; ri++) {
            den[ri] = 0.f; num[ri] = 0.f; emax[ri] = 0.f; emp[ri] = 0.f;
        }

        mbar_wait(barQ, qph); qph ^= 1;

        for (int j = c0; j < c1; j++, tt++) {
            // prefetch A tile tt+3 (A depends only on col — crosses segments)
            if (tid == 0 && tt + 3 < njobs)
                issue_a(smb, (tt + 3) & 3, (start + tt + 3) % ncol, qid, rnk);

            const int slot = tt & 3;
            mbar_wait(smb + SM_BAR + 8 + slot * 8, (tt >> 2) & 1);

            const uint32_t sma = smb + SM_A(slot);
            const uint32_t smq = smb + SM_Q;

            float acc[2][4][4];
            #pragma unroll
            for (int mi = 0; mi < 2; mi++)
                #pragma unroll
                for (int ni = 0; ni < 4; ni++)
                    #pragma unroll
                    for (int k = 0; k < 4; k++) acc[mi][ni][k] = 0.f;

            #pragma unroll
            for (int s = 0; s < 8; s++) {
                const int haQ = (s >> 2) << 15;          // Q k-half stride 32KB
                const int haA = (s >> 2) << 13;          // A k-half stride 8KB
                const int cb = (s & 3) << 1;
                const int tA = (((cb | subA) ^ x) << 4) + haQ;
                const int tB = (((cb | subB) ^ x) << 4) + haA;
                uint32_t ah[2][4], bh[2][4];
                #pragma unroll
                for (int mi = 0; mi < 2; mi++)
                    LDSM4(ah[mi], smq + rAoff[mi] + tA);
                #pragma unroll
                for (int n2 = 0; n2 < 2; n2++)
                    LDSM4(bh[n2], sma + rBoff[n2] + tB);
                #pragma unroll
                for (int mi = 0; mi < 2; mi++)
                    #pragma unroll
                    for (int ni = 0; ni < 4; ni++) {
                        const uint32_t* bhf = &bh[ni >> 1][(ni & 1) * 2];
                        MMAI(acc[mi][ni], ah[mi], bhf);   // q * a
                    }
            }

            // ---- epilogue (overlap across warps via occupancy) ----
            {
                const int*   idsb = (const int*)(sm + SM_IDS(slot));
                const float* rkb  = (const float*)(sm + SM_RNK(slot));
                int ids8[8];
                float w8[8];
                #pragma unroll
                for (int ni = 0; ni < 4; ni++)
                    #pragma unroll
                    for (int jj = 0; jj < 2; jj++) {
                        int cl = wn * 32 + ni * 8 + (l & 3) * 2 + jj;
                        ids8[ni * 2 + jj] = idsb[cl];
                        w8[ni * 2 + jj]   = 1.0f - 0.1f * rkb[cl];
                    }
                #pragma unroll
                for (int mi = 0; mi < 2; mi++)
                    #pragma unroll
                    for (int h = 0; h < 2; h++) {
                        const int ri = mi * 2 + h;
                        #pragma unroll
                        for (int ni = 0; ni < 4; ni++)
                            #pragma unroll
                            for (int jj = 0; jj < 2; jj++) {
                                const int cj = ni * 2 + jj;
                                float e = ex2f(acc[mi][ni][h * 2 + jj]);
                                den[ri] += e;
                                float em = (ids8[cj] == qrow[ri]) ? e : 0.0f;
                                num[ri] = fmaf(w8[cj], em, num[ri]);
                                emax[ri] = fmaxf(emax[ri], e);
                                emp[ri]  = fmaxf(emp[ri], em);
                            }
                    }
            }
            __syncthreads();   // release slot for TMA reuse at tt+4
        }

        // ---- reduce: lane quads, then 2 wn warps via smem, then atomics ----
        #pragma unroll
        for (int ri = 0; ri < 4; ri++) {
            #pragma unroll
            for (int o = 1; o <= 2; o <<= 1) {
                den[ri]  += __shfl_xor_sync(0xffffffffu, den[ri], o);
                num[ri]  += __shfl_xor_sync(0xffffffffu, num[ri], o);
                emax[ri]  = fmaxf(emax[ri], __shfl_xor_sync(0xffffffffu, emax[ri], o));
                emp[ri]   = fmaxf(emp[ri],  __shfl_xor_sync(0xffffffffu, emp[ri],  o));
            }
        }
        float* sden = (float*)(sm + SM_RED);              // [2][256]
        float* snum = (float*)(sm + SM_RED + 2048);
        float* smx  = (float*)(sm + SM_RED + 4096);
        float* smp  = (float*)(sm + SM_RED + 6144);
        if ((l & 3) == 0) {
            #pragma unroll
            for (int mi = 0; mi < 2; mi++)
                #pragma unroll
                for (int h = 0; h < 2; h++) {
                    int ri = mi * 2 + h;
                    int row = wm * 32 + mi * 16 + (l >> 2) + h * 8;
                    sden[wn * 256 + row] = den[ri];
                    snum[wn * 256 + row] = num[ri];
                    smx [wn * 256 + row] = emax[ri];
                    smp [wn * 256 + row] = emp[ri];
                }
        }
        __syncthreads();
        if (tid < 256) {
            float d = 0.f, n = 0.f, mx = 0.f, mp = 0.f;
            #pragma unroll
            for (int w = 0; w < 2; w++) {
                d += sden[w * 256 + tid];
                n += snum[w * 256 + tid];
                mx = fmaxf(mx, smx[w * 256 + tid]);
                mp = fmaxf(mp, smp[w * 256 + tid]);
            }
            atomicAdd(&g_den[rowbase + tid], d);
            atomicAdd(&g_num[rowbase + tid], n);
            atomicMax(&g_emax[rowbase + tid], __float_as_int(mx));
            atomicMax(&g_emp[rowbase + tid], __float_as_int(mp));
        }
        __syncthreads();   // Q buf free before next segment's TMA
    }

    // ---- last CTA computes loss + accuracy ----
    __threadfence();
    int* sflag = (int*)(sm + SM_BAR + 48);
    if (tid == 0) *sflag = (atomicAdd(&g_done, 1) == NSM - 1) ? 1 : 0;
    __syncthreads();
    if (*sflag) {
        float ls = 0.f;
        int cs = 0;
        for (int r = tid; r < B; r += NTH) {
            float d  = __ldcg(&g_den[r]);
            float n  = __ldcg(&g_num[r]);
            float mx = __int_as_float(__ldcg(&g_emax[r]));
            float mp = __int_as_float(__ldcg(&g_emp[r]));
            ls += -logf(n / d + 1e-8f);
            cs += (mp >= mx) ? 1 : 0;
        }
        float* sf = (float*)(sm + SM_RED);
        int*   si = (int*)(sm + SM_RED + 2048);
        sf[tid] = ls; si[tid] = cs;
        __syncthreads();
        for (int o = NTH / 2; o > 0; o >>= 1) {
            if (tid < o) { sf[tid] += sf[tid + o]; si[tid] += si[tid + o]; }
            __syncthreads();
        }
        if (tid == 0) {
            out[0] = sf[0] / (float)B;
            if (osz > 1) out[1] = (float)si[0] / (float)B;
        }
    }
}

extern "C" void kernel_launch(void* const* d_in, const int* in_sizes, int n_in,
                              void* d_out, int out_size) {
    const float* Q   = (const float*)d_in[0];
    const float* A   = (const float*)d_in[1];
    const int*   qid = (const int*)d_in[2];
    const float* rnk = (const float*)d_in[3];
    const int B = in_sizes[2];
    const int n8 = B * DD / 8;

    mpl_prep<<<(n8 + 255) / 256, 256>>>((const float4*)Q, (const float4*)A, n8);

    cudaFuncSetAttribute(mpl_main, cudaFuncAttributeMaxDynamicSharedMemorySize,
                         SMEM_TOTAL);
    mpl_main<<<NSM, NTH, SMEM_TOTAL>>>(qid, rnk, (float*)d_out, B, out_size);
}

// round 17
// speedup vs baseline: 1.5540x; 1.0936x over previous
#include <cuda_runtime.h>
#include <cuda_fp16.h>
#include <cstdint>

#define MAXB 8192
#define DD   128
#define NTH  512
#define NSM  148
#define ROWT 256
#define COLT 64
#define NSLOT 6

// ---------------- global scratch (no allocations allowed) ----------------
__device__ __align__(1024) unsigned char g_qtile[2 * 1024 * 1024]; // 32 blks x 64KB (Q fp16)
__device__ __align__(1024) unsigned char g_atile[2 * 1024 * 1024]; // 128 blks x 16KB (A fp16)
__device__ float g_den[MAXB], g_num[MAXB];
__device__ int   g_emax[MAXB], g_emp[MAXB];
__device__ int   g_done;

// ---------------- smem layout ----------------
#define SM_Q     0                        // 64KB: h0 32K | h1 32K
#define SM_A(b)  (65536 + (b) * 16384)    // 6 bufs: h0 8K | h1 8K
#define SM_IDS(s) (163840 + (s) * 256)    // 6 slots x 64 ids
#define SM_RNK(s) (165376 + (s) * 256)
#define SM_BAR   166912                   // barQ +0, A full bars +8..+55, flag +64
#define SM_RED   167040                   // 8KB reduction area
#define SMEM_TOTAL 175296

static __device__ __forceinline__ unsigned su32(const void* p) {
    return (unsigned)__cvta_generic_to_shared(p);
}
static __device__ __forceinline__ void mbar_init(uint32_t bar, int cnt) {
    asm volatile("mbarrier.init.shared.b64 [%0], %1;" :: "r"(bar), "r"(cnt) : "memory");
}
static __device__ __forceinline__ void mbar_expect(uint32_t bar, uint32_t bytes) {
    asm volatile("mbarrier.arrive.expect_tx.shared.b64 _, [%0], %1;"
                 :: "r"(bar), "r"(bytes) : "memory");
}
static __device__ __forceinline__ void bulk_g2s(uint32_t dst, const void* src,
                                                uint32_t bytes, uint32_t bar) {
    asm volatile(
        "cp.async.bulk.shared::cta.global.mbarrier::complete_tx::bytes [%0], [%1], %2, [%3];"
        :: "r"(dst), "l"(src), "r"(bytes), "r"(bar) : "memory");
}
static __device__ __forceinline__ void mbar_wait(uint32_t bar, int parity) {
    asm volatile(
        "{\n\t.reg .pred P;\n\t"
        "WL_%=:\n\t"
        "mbarrier.try_wait.parity.shared.b64 P, [%0], %1;\n\t"
        "@P bra.uni WD_%=;\n\t"
        "bra.uni WL_%=;\n\t"
        "WD_%=:\n\t}"
        :: "r"(bar), "r"(parity) : "memory");
}
static __device__ __forceinline__ float ex2f(float x) {
    float r;
    asm("ex2.approx.ftz.f32 %0, %1;" : "=f"(r) : "f"(x));
    return r;
}

// swizzled offset inside one k-half region (row r, 16B chunk c 0..7)
static __device__ __forceinline__ int halfoff(int r, int c) {
    return r * 128 + ((c ^ (r & 7)) << 4);
}

#define LDSM4(rg, ad) asm volatile( \
    "ldmatrix.sync.aligned.m8n8.x4.shared.b16 {%0,%1,%2,%3}, [%4];" \
    : "=r"((rg)[0]), "=r"((rg)[1]), "=r"((rg)[2]), "=r"((rg)[3]) : "r"(ad))
#define MMAI(dd, aa, bb) asm volatile( \
    "mma.sync.aligned.m16n8k16.row.col.f32.f16.f16.f32 " \
    "{%0,%1,%2,%3}, {%4,%5,%6,%7}, {%8,%9}, {%0,%1,%2,%3};" \
    : "+f"((dd)[0]), "+f"((dd)[1]), "+f"((dd)[2]), "+f"((dd)[3]) \
    : "r"((aa)[0]), "r"((aa)[1]), "r"((aa)[2]), "r"((aa)[3]), \
      "r"((bb)[0]), "r"((bb)[1]))

// ---------- prep: fp32 -> fp16 (Q prescaled by log2(e); A plain) pre-swizzled ----------
extern "C" __global__ void mpl_prep(const float4* __restrict__ Q4,
                                    const float4* __restrict__ A4, int n8) {
    int i = blockIdx.x * blockDim.x + threadIdx.x;   // one 16B fp16 chunk (8 elems)
    if (i < n8) {
        float4 qa = Q4[2 * i], qb = Q4[2 * i + 1];
        float4 aa = A4[2 * i], ab = A4[2 * i + 1];
        float qv[8] = {qa.x, qa.y, qa.z, qa.w, qb.x, qb.y, qb.z, qb.w};
        float av[8] = {aa.x, aa.y, aa.z, aa.w, ab.x, ab.y, ab.z, ab.w};
        __align__(16) __half qh8[8], ah8[8];
        #pragma unroll
        for (int k = 0; k < 8; k++) {
            qh8[k] = __float2half(qv[k] * 1.4426950408889634f);  // fold log2e
            ah8[k] = __float2half(av[k]);
        }
        const int r = i >> 4, cc = i & 15;
        {   // Q tile image: blk 64KB = [h0 32K | h1 32K]
            int rt = r >> 8, rl = r & 255;
            size_t off = (size_t)rt * 65536 + ((cc >> 3) << 15) + halfoff(rl, cc & 7);
            *(uint4*)(g_qtile + off) = *(uint4*)qh8;
        }
        {   // A tile image: blk 16KB = [h0 8K | h1 8K]
            int j = r >> 6, rl = r & 63;
            size_t off = (size_t)j * 16384 + ((cc >> 3) << 13) + halfoff(rl, cc & 7);
            *(uint4*)(g_atile + off) = *(uint4*)ah8;
        }
    }
    if (i < MAXB) {
        g_den[i] = 0.f; g_num[i] = 0.f; g_emax[i] = 0; g_emp[i] = 0;
    }
    if (i == 0) g_done = 0;
}

static __device__ __forceinline__ void issue_a(uint32_t smb, int slot, int col,
                                               const int* qid, const float* rnk) {
    const uint32_t bar = smb + SM_BAR + 8 + slot * 8;
    mbar_expect(bar, 16384 + 512);
    bulk_g2s(smb + SM_A(slot), g_atile + (size_t)col * 16384, 16384, bar);
    bulk_g2s(smb + SM_IDS(slot), qid + col * COLT, 256, bar);
    bulk_g2s(smb + SM_RNK(slot), rnk + col * COLT, 256, bar);
}

// -------------------- main: 16-warp persistent fused GEMM + softmax-ratio --------------------
extern "C" __global__ void __launch_bounds__(NTH, 1)
mpl_main(const int* __restrict__ qid, const float* __restrict__ rnk,
         float* __restrict__ out, int B, int osz) {
    extern __shared__ __align__(128) char sm[];
    const uint32_t smb = su32(sm);
    const int tid = threadIdx.x, l = tid & 31, wid = tid >> 5;
    const int wm = wid >> 1, wn = wid & 1;       // 8x2 warp grid (32x32 per warp)
    const int ncol = B / COLT, nrow = B / ROWT;
    const long long total = (long long)nrow * ncol;
    const int start = (int)(total * blockIdx.x / NSM);
    const int end   = (int)(total * (blockIdx.x + 1) / NSM);
    const int njobs = end - start;

    const uint32_t barQ = smb + SM_BAR;
    if (tid == 0) {
        mbar_init(barQ, 1);
        #pragma unroll
        for (int b = 0; b < NSLOT; b++) mbar_init(smb + SM_BAR + 8 + b * 8, 1);
    }
    __syncthreads();

    int pf = 0;   // TMA issue cursor (valid in tid0 only)
    if (tid == 0) {
        int lim = min(njobs, NSLOT);
        while (pf < lim) { issue_a(smb, pf % NSLOT, (start + pf) % ncol, qid, rnk); pf++; }
    }

    const int x = l & 7, subA = l >> 4, subB = (l >> 3) & 1;
    int rAoff[2], rBoff[2];
    #pragma unroll
    for (int mi = 0; mi < 2; mi++) rAoff[mi] = (wm * 32 + mi * 16 + (l & 15)) * 128;
    #pragma unroll
    for (int n2 = 0; n2 < 2; n2++)
        rBoff[n2] = (wn * 32 + n2 * 16 + ((l >> 4) << 3) + (l & 7)) * 128;

    int qph = 0;
    int tt = 0;          // flat tile counter: slot = tt%6, phase = (tt/6)&1
    int pos = start;
    while (pos < end) {
        const int rt = pos / ncol;
        const int c0 = pos - rt * ncol;
        const int c1 = min(ncol, c0 + (end - pos));
        pos += c1 - c0;
        const int rowbase = rt * ROWT;

        if (tid == 0) {       // Q tile for this segment (prior segment fully synced)
            mbar_expect(barQ, 65536);
            const unsigned char* qs = g_qtile + (size_t)rt * 65536;
            #pragma unroll
            for (int k = 0; k < 4; k++)
                bulk_g2s(smb + SM_Q + k * 16384, qs + k * 16384, 16384, barQ);
        }

        int qrow[4];
        #pragma unroll
        for (int mi = 0; mi < 2; mi++)
            #pragma unroll
            for (int h = 0; h < 2; h++)
                qrow[mi * 2 + h] = qid[rowbase + wm * 32 + mi * 16 + (l >> 2) + h * 8];

        float den[4], num[4], emax[4], emp[4];
        #pragma unroll
        for (int ri = 0; ri < 4; ri++) {
            den[ri] = 0.f; num[ri] = 0.f; emax[ri] = 0.f; emp[ri] = 0.f;
        }

        mbar_wait(barQ, qph); qph ^= 1;

        int j = c0;
        while (j < c1) {
            const int take = min(2, c1 - j);
            for (int u = 0; u < take; u++, j++, tt++) {
                const int slot = tt % NSLOT;
                mbar_wait(smb + SM_BAR + 8 + slot * 8, (tt / NSLOT) & 1);

                const uint32_t sma = smb + SM_A(slot);
                const uint32_t smq = smb + SM_Q;

                float acc[2][4][4];
                #pragma unroll
                for (int mi = 0; mi < 2; mi++)
                    #pragma unroll
                    for (int ni = 0; ni < 4; ni++)
                        #pragma unroll
                        for (int k = 0; k < 4; k++) acc[mi][ni][k] = 0.f;

                #pragma unroll
                for (int s = 0; s < 8; s++) {
                    const int haQ = (s >> 2) << 15;
                    const int haA = (s >> 2) << 13;
                    const int cb = (s & 3) << 1;
                    const int tA = (((cb | subA) ^ x) << 4) + haQ;
                    const int tB = (((cb | subB) ^ x) << 4) + haA;
                    uint32_t ah[2][4], bh[2][4];
                    #pragma unroll
                    for (int mi = 0; mi < 2; mi++)
                        LDSM4(ah[mi], smq + rAoff[mi] + tA);
                    #pragma unroll
                    for (int n2 = 0; n2 < 2; n2++)
                        LDSM4(bh[n2], sma + rBoff[n2] + tB);
                    #pragma unroll
                    for (int mi = 0; mi < 2; mi++)
                        #pragma unroll
                        for (int ni = 0; ni < 4; ni++) {
                            const uint32_t* bhf = &bh[ni >> 1][(ni & 1) * 2];
                            MMAI(acc[mi][ni], ah[mi], bhf);
                        }
                }

                // ---- epilogue: dense (exp/den/emax) + rare positive branch ----
                {
                    const int*   idsb = (const int*)(sm + SM_IDS(slot));
                    const float* rkb  = (const float*)(sm + SM_RNK(slot));
                    int ids8[8];
                    float w8[8];
                    #pragma unroll
                    for (int ni = 0; ni < 4; ni++)
                        #pragma unroll
                        for (int jj = 0; jj < 2; jj++) {
                            int cl = wn * 32 + ni * 8 + (l & 3) * 2 + jj;
                            ids8[ni * 2 + jj] = idsb[cl];
                            w8[ni * 2 + jj]   = 1.0f - 0.1f * rkb[cl];
                        }
                    #pragma unroll
                    for (int mi = 0; mi < 2; mi++)
                        #pragma unroll
                        for (int h = 0; h < 2; h++) {
                            const int ri = mi * 2 + h;
                            // dense pass: every element
                            #pragma unroll
                            for (int ni = 0; ni < 4; ni++)
                                #pragma unroll
                                for (int jj = 0; jj < 2; jj++) {
                                    float e = ex2f(acc[mi][ni][h * 2 + jj]);
                                    den[ri] += e;
                                    emax[ri] = fmaxf(emax[ri], e);
                                }
                            // rare pass: only if this thread sees a positive
                            bool anyp = false;
                            #pragma unroll
                            for (int cj = 0; cj < 8; cj++)
                                anyp = anyp || (ids8[cj] == qrow[ri]);
                            if (anyp) {
                                #pragma unroll
                                for (int ni = 0; ni < 4; ni++)
                                    #pragma unroll
                                    for (int jj = 0; jj < 2; jj++) {
                                        const int cj = ni * 2 + jj;
                                        if (ids8[cj] == qrow[ri]) {
                                            float e = ex2f(acc[mi][ni][h * 2 + jj]);
                                            num[ri] = fmaf(w8[cj], e, num[ri]);
                                            emp[ri] = fmaxf(emp[ri], e);
                                        }
                                    }
                            }
                        }
                }
            }
            __syncthreads();   // pair done: slots <= tt-1 consumed
            if (tid == 0) {
                int lim = min(njobs, tt + NSLOT);
                while (pf < lim) {
                    issue_a(smb, pf % NSLOT, (start + pf) % ncol, qid, rnk);
                    pf++;
                }
            }
        }

        // ---- reduce: lane quads, then 2 wn warps via smem, then atomics ----
        #pragma unroll
        for (int ri = 0; ri < 4; ri++) {
            #pragma unroll
            for (int o = 1; o <= 2; o <<= 1) {
                den[ri]  += __shfl_xor_sync(0xffffffffu, den[ri], o);
                num[ri]  += __shfl_xor_sync(0xffffffffu, num[ri], o);
                emax[ri]  = fmaxf(emax[ri], __shfl_xor_sync(0xffffffffu, emax[ri], o));
                emp[ri]   = fmaxf(emp[ri],  __shfl_xor_sync(0xffffffffu, emp[ri],  o));
            }
        }
        float* sden = (float*)(sm + SM_RED);              // [2][256]
        float* snum = (float*)(sm + SM_RED + 2048);
        float* smx  = (float*)(sm + SM_RED + 4096);
        float* smp  = (float*)(sm + SM_RED + 6144);
        if ((l & 3) == 0) {
            #pragma unroll
            for (int mi = 0; mi < 2; mi++)
                #pragma unroll
                for (int h = 0; h < 2; h++) {
                    int ri = mi * 2 + h;
                    int row = wm * 32 + mi * 16 + (l >> 2) + h * 8;
                    sden[wn * 256 + row] = den[ri];
                    snum[wn * 256 + row] = num[ri];
                    smx [wn * 256 + row] = emax[ri];
                    smp [wn * 256 + row] = emp[ri];
                }
        }
        __syncthreads();
        if (tid < 256) {
            float d = 0.f, n = 0.f, mx = 0.f, mp = 0.f;
            #pragma unroll
            for (int w = 0; w < 2; w++) {
                d += sden[w * 256 + tid];
                n += snum[w * 256 + tid];
                mx = fmaxf(mx, smx[w * 256 + tid]);
                mp = fmaxf(mp, smp[w * 256 + tid]);
            }
            atomicAdd(&g_den[rowbase + tid], d);
            atomicAdd(&g_num[rowbase + tid], n);
            atomicMax(&g_emax[rowbase + tid], __float_as_int(mx));
            atomicMax(&g_emp[rowbase + tid], __float_as_int(mp));
        }
        __syncthreads();   // Q buf free before next segment's TMA
    }

    // ---- last CTA computes loss + accuracy ----
    __threadfence();
    int* sflag = (int*)(sm + SM_BAR + 64);
    if (tid == 0) *sflag = (atomicAdd(&g_done, 1) == NSM - 1) ? 1 : 0;
    __syncthreads();
    if (*sflag) {
        float ls = 0.f;
        int cs = 0;
        for (int r = tid; r < B; r += NTH) {
            float d  = __ldcg(&g_den[r]);
            float n  = __ldcg(&g_num[r]);
            float mx = __int_as_float(__ldcg(&g_emax[r]));
            float mp = __int_as_float(__ldcg(&g_emp[r]));
            ls += -logf(n / d + 1e-8f);
            cs += (mp >= mx) ? 1 : 0;
        }
        float* sf = (float*)(sm + SM_RED);
        int*   si = (int*)(sm + SM_RED + 2048);
        sf[tid] = ls; si[tid] = cs;
        __syncthreads();
        for (int o = NTH / 2; o > 0; o >>= 1) {
            if (tid < o) { sf[tid] += sf[tid + o]; si[tid] += si[tid + o]; }
            __syncthreads();
        }
        if (tid == 0) {
            out[0] = sf[0] / (float)B;
            if (osz > 1) out[1] = (float)si[0] / (float)B;
        }
    }
}

extern "C" void kernel_launch(void* const* d_in, const int* in_sizes, int n_in,
                              void* d_out, int out_size) {
    const float* Q   = (const float*)d_in[0];
    const float* A   = (const float*)d_in[1];
    const int*   qid = (const int*)d_in[2];
    const float* rnk = (const float*)d_in[3];
    const int B = in_sizes[2];
    const int n8 = B * DD / 8;

    mpl_prep<<<(n8 + 255) / 256, 256>>>((const float4*)Q, (const float4*)A, n8);

    cudaFuncSetAttribute(mpl_main, cudaFuncAttributeMaxDynamicSharedMemorySize,
                         SMEM_TOTAL);
    mpl_main<<<NSM, NTH, SMEM_TOTAL>>>(qid, rnk, (float*)d_out, B, out_size);
}